// round 1
// baseline (speedup 1.0000x reference)
#include <cuda_runtime.h>
#include <math.h>

// ---------------- problem constants ----------------
#define NB   3
#define Bc   4
#define Tt   512
#define Nf   256
#define Dd   1024
#define DXFc 512
#define Ee   1024
#define Hh   16
#define HDc  64
#define SQ   (NB*Tt)   // 1536
#define SKk  (NB*Nf)   // 768
#define BHc  (Bc*Hh)   // 64
#define EPSV 1e-6f

// ---------------- scratch (static device globals; no allocation) ----------------
__device__ float g_mod_x [NB*Bc*2*Dd];          // (NB,B,2D) adaLN scale/shift for x
__device__ float g_mod_xf[NB*Bc*2*DXFc];        // (NB,B,2DXF)
__device__ float g_xn [NB*Bc*Tt*Dd];            // normalized+modulated x
__device__ float g_xfn[NB*Bc*Nf*DXFc];          // normalized+modulated xf
__device__ float g_Qh[(size_t)BHc*SQ*HDc];      // (B*H, Sq, 64)
__device__ float g_Kh[(size_t)BHc*SKk*HDc];     // (B*H, Sk, 64)
__device__ float g_Vh[(size_t)BHc*SKk*HDc];
__device__ float g_att[(size_t)Bc*SQ*Dd];       // (B, Sq, D) attention output

// ---------------- kernel 1: adaLN modulation vectors ----------------
// out[n][b][j] = sum_e silu(emb[b,e]) * w[n,j,e] + bias[n,j]
__global__ __launch_bounds__(256) void adaln_mod_kernel(
    const float* __restrict__ emb, const float* __restrict__ w,
    const float* __restrict__ bvec, float* __restrict__ out, int twoD)
{
    __shared__ float se[Ee];
    int b = blockIdx.y, n = blockIdx.z;
    int tid = threadIdx.x;
    for (int i = tid*4; i < Ee; i += 256*4) {
        float4 v = *(const float4*)(emb + (size_t)b*Ee + i);
        se[i+0] = v.x / (1.f + __expf(-v.x));
        se[i+1] = v.y / (1.f + __expf(-v.y));
        se[i+2] = v.z / (1.f + __expf(-v.z));
        se[i+3] = v.w / (1.f + __expf(-v.w));
    }
    __syncthreads();
    int j = blockIdx.x*256 + tid;
    const float* wr = w + ((size_t)n*twoD + j)*Ee;
    float acc = 0.f;
    #pragma unroll 8
    for (int e = 0; e < Ee; e += 4) {
        float4 wv = *(const float4*)(wr + e);
        acc += se[e]*wv.x + se[e+1]*wv.y + se[e+2]*wv.z + se[e+3]*wv.w;
    }
    out[((size_t)n*Bc + b)*twoD + j] = acc + bvec[(size_t)n*twoD + j];
}

// ---------------- kernel 2: LayerNorm + modulate ----------------
// one block per row; xn = LN(x) * (1 + scale) + shift
__global__ __launch_bounds__(256) void ln_mod_kernel(
    const float* __restrict__ xa, const float* __restrict__ xb,
    const float* __restrict__ xc, const float* __restrict__ mod,
    float* __restrict__ xn, int dim, int rows_per_n, int rows_per_b)
{
    int r  = blockIdx.x;
    int n  = r / rows_per_n;
    int rr = r - n*rows_per_n;
    int b  = rr / rows_per_b;
    const float* xp = (n == 0 ? xa : (n == 1 ? xb : xc)) + (size_t)rr*dim;
    int tid = threadIdx.x;

    float s1 = 0.f, s2 = 0.f;
    for (int d = tid*4; d < dim; d += 1024) {
        float4 v = *(const float4*)(xp + d);
        s1 += v.x + v.y + v.z + v.w;
        s2 += v.x*v.x + v.y*v.y + v.z*v.z + v.w*v.w;
    }
    #pragma unroll
    for (int off = 16; off; off >>= 1) {
        s1 += __shfl_xor_sync(0xffffffffu, s1, off);
        s2 += __shfl_xor_sync(0xffffffffu, s2, off);
    }
    __shared__ float rs1[8], rs2[8];
    int wid = tid >> 5, lane = tid & 31;
    if (!lane) { rs1[wid] = s1; rs2[wid] = s2; }
    __syncthreads();
    s1 = rs1[0]+rs1[1]+rs1[2]+rs1[3]+rs1[4]+rs1[5]+rs1[6]+rs1[7];
    s2 = rs2[0]+rs2[1]+rs2[2]+rs2[3]+rs2[4]+rs2[5]+rs2[6]+rs2[7];

    float inv = 1.f / (float)dim;
    float mu  = s1 * inv;
    float var = s2 * inv - mu*mu;
    float rstd = rsqrtf(var + EPSV);

    const float* sc = mod + ((size_t)n*Bc + b)*2*dim;
    const float* sh = sc + dim;
    float* op = xn + (size_t)r*dim;
    for (int d = tid*4; d < dim; d += 1024) {
        float4 v = *(const float4*)(xp + d);
        float4 s = *(const float4*)(sc + d);
        float4 h = *(const float4*)(sh + d);
        float4 o;
        o.x = (v.x - mu)*rstd*(1.f + s.x) + h.x;
        o.y = (v.y - mu)*rstd*(1.f + s.y) + h.y;
        o.z = (v.z - mu)*rstd*(1.f + s.z) + h.z;
        o.w = (v.w - mu)*rstd*(1.f + s.w) + h.w;
        *(float4*)(op + d) = o;
    }
}

// ---------------- kernel 3: batched SGEMM  C = A * W^T + bias ----------------
// A rows are K-contiguous; W is (NB, Nout, K) row-major (also K-contiguous).
// MODE 0: A = activation per-n contiguous [n][M][K]; output scattered to head
//         layout  C[((b*H+h)*NB*L + n*L + l)*64 + hd]   (o = h*64+hd, m = b*L+l)
// MODE 1: A = g_att rows (b*NB+n)*L + t with m = b*L+t; output C[n*M*Nout + m*Nout + o]
template<int MODE>
__global__ __launch_bounds__(256) void gemm_kernel(
    const float* __restrict__ A, const float* __restrict__ W,
    const float* __restrict__ bias, float* __restrict__ C,
    int M, int Nout, int K, int L)
{
    __shared__ __align__(16) float As[8][132];
    __shared__ __align__(16) float Bs[8][132];

    int n  = blockIdx.z;
    int mt = blockIdx.x, nt = blockIdx.y;
    int tid = threadIdx.x;
    int lrow = tid >> 1;
    int lk   = (tid & 1) * 4;
    int m0 = mt * 128;

    int mrow = m0 + lrow;
    const float* aptr;
    if (MODE == 0) {
        aptr = A + ((size_t)n*M + mrow)*K + lk;
    } else {
        int bq = mrow / L;
        int tq = mrow - bq*L;
        aptr = A + ((size_t)(bq*NB + n)*L + tq)*K + lk;
    }
    const float* wptr = W + ((size_t)n*Nout + nt*128 + lrow)*K + lk;

    int tx = tid & 15, ty = tid >> 4;
    float acc[8][8];
    #pragma unroll
    for (int i = 0; i < 8; i++)
        #pragma unroll
        for (int j = 0; j < 8; j++) acc[i][j] = 0.f;

    float4 av = *(const float4*)(aptr);
    float4 wv = *(const float4*)(wptr);

    for (int k0 = 0; k0 < K; k0 += 8) {
        As[lk+0][lrow] = av.x; As[lk+1][lrow] = av.y;
        As[lk+2][lrow] = av.z; As[lk+3][lrow] = av.w;
        Bs[lk+0][lrow] = wv.x; Bs[lk+1][lrow] = wv.y;
        Bs[lk+2][lrow] = wv.z; Bs[lk+3][lrow] = wv.w;
        __syncthreads();

        float4 av2 = av, wv2 = wv;
        if (k0 + 8 < K) {
            av2 = *(const float4*)(aptr + k0 + 8);
            wv2 = *(const float4*)(wptr + k0 + 8);
        }

        #pragma unroll
        for (int kk = 0; kk < 8; kk++) {
            float4 a0 = *(const float4*)&As[kk][ty*4];
            float4 a1 = *(const float4*)&As[kk][64 + ty*4];
            float4 b0 = *(const float4*)&Bs[kk][tx*4];
            float4 b1 = *(const float4*)&Bs[kk][64 + tx*4];
            float ar[8] = {a0.x,a0.y,a0.z,a0.w,a1.x,a1.y,a1.z,a1.w};
            float br[8] = {b0.x,b0.y,b0.z,b0.w,b1.x,b1.y,b1.z,b1.w};
            #pragma unroll
            for (int i = 0; i < 8; i++)
                #pragma unroll
                for (int j = 0; j < 8; j++)
                    acc[i][j] += ar[i]*br[j];
        }
        __syncthreads();
        av = av2; wv = wv2;
    }

    // epilogue
    float bb[8];
    #pragma unroll
    for (int jj = 0; jj < 8; jj++) {
        int col = nt*128 + ((jj < 4) ? (tx*4 + jj) : (64 + tx*4 + jj - 4));
        bb[jj] = bias[(size_t)n*Nout + col];
    }
    #pragma unroll
    for (int ii = 0; ii < 8; ii++) {
        int row = m0 + ((ii < 4) ? (ty*4 + ii) : (64 + ty*4 + ii - 4));
        #pragma unroll
        for (int jg = 0; jg < 2; jg++) {
            int col = nt*128 + jg*64 + tx*4;
            float4 o;
            o.x = acc[ii][jg*4+0] + bb[jg*4+0];
            o.y = acc[ii][jg*4+1] + bb[jg*4+1];
            o.z = acc[ii][jg*4+2] + bb[jg*4+2];
            o.w = acc[ii][jg*4+3] + bb[jg*4+3];
            if (MODE == 0) {
                int bq = row / L;  int l = row - bq*L;
                int h = col >> 6;  int hd = col & 63;
                size_t idx = (((size_t)(bq*Hh + h))*((size_t)NB*L) + (size_t)n*L + l)*HDc + hd;
                *(float4*)(C + idx) = o;
            } else {
                size_t idx = ((size_t)n*M + row)*Nout + col;
                *(float4*)(C + idx) = o;
            }
        }
    }
}

// ---------------- kernel 4: flash attention (fp32) ----------------
// grid (Sq/64, B*H); 64-query tiles, 32-key tiles, online softmax.
__global__ __launch_bounds__(256) void attn_kernel(
    const float* __restrict__ Q, const float* __restrict__ K,
    const float* __restrict__ V, float* __restrict__ O)
{
    __shared__ __align__(16) float Qs[64*64];     // [q][d], scaled by 1/8
    __shared__ __align__(16) float Kst[64*36];    // [d][k] transposed, stride 36
    __shared__ __align__(16) float Ps[32*68];     // [k][q] transposed, stride 68
    __shared__ __align__(16) float Vs[32*64];     // [k][d]
    __shared__ float sm[64], sl[64], srs[64];

    int qt = blockIdx.x, bh = blockIdx.y;
    int tid = threadIdx.x;

    const float* Qb = Q + ((size_t)bh*SQ + qt*64)*HDc;
    for (int i = tid; i < 64*16; i += 256) {
        int r = i >> 4, c = (i & 15) * 4;
        float4 v = *(const float4*)(Qb + r*64 + c);
        v.x *= 0.125f; v.y *= 0.125f; v.z *= 0.125f; v.w *= 0.125f; // 1/sqrt(64)
        *(float4*)(Qs + r*64 + c) = v;
    }
    if (tid < 64) { sm[tid] = -3.0e38f; sl[tid] = 0.f; }

    int sq = (tid >> 3) * 2;      // S-stage: 2 query rows
    int sk = (tid & 7) * 4;       // S-stage: 4 key cols
    int py = tid >> 4, px = tid & 15;  // PV-stage: 4 q rows, 4 d cols

    float acc[4][4] = {};
    __syncthreads();

    for (int kt = 0; kt < SKk/32; kt++) {
        const float* Kb = K + ((size_t)bh*SKk + kt*32)*HDc;
        const float* Vb = V + ((size_t)bh*SKk + kt*32)*HDc;
        for (int i = tid; i < 32*16; i += 256) {
            int r = i >> 4, c = (i & 15) * 4;
            float4 kv = *(const float4*)(Kb + r*64 + c);
            Kst[(c+0)*36 + r] = kv.x;
            Kst[(c+1)*36 + r] = kv.y;
            Kst[(c+2)*36 + r] = kv.z;
            Kst[(c+3)*36 + r] = kv.w;
            *(float4*)(Vs + r*64 + c) = *(const float4*)(Vb + r*64 + c);
        }
        __syncthreads();

        // S = Q K^T  (per-thread 2x4)
        float s0[4] = {}, s1[4] = {};
        #pragma unroll
        for (int d4 = 0; d4 < 16; d4++) {
            float4 qa = *(const float4*)(Qs + sq*64 + d4*4);
            float4 qb = *(const float4*)(Qs + (sq+1)*64 + d4*4);
            float qa_s[4] = {qa.x, qa.y, qa.z, qa.w};
            float qb_s[4] = {qb.x, qb.y, qb.z, qb.w};
            #pragma unroll
            for (int dd = 0; dd < 4; dd++) {
                float4 kv = *(const float4*)(Kst + (d4*4 + dd)*36 + sk);
                s0[0] += qa_s[dd]*kv.x; s0[1] += qa_s[dd]*kv.y;
                s0[2] += qa_s[dd]*kv.z; s0[3] += qa_s[dd]*kv.w;
                s1[0] += qb_s[dd]*kv.x; s1[1] += qb_s[dd]*kv.y;
                s1[2] += qb_s[dd]*kv.z; s1[3] += qb_s[dd]*kv.w;
            }
        }

        // online softmax per query row (row owned by 8 consecutive lanes)
        #pragma unroll
        for (int i = 0; i < 2; i++) {
            float* s = (i == 0) ? s0 : s1;
            int q = sq + i;
            float mx = fmaxf(fmaxf(s[0], s[1]), fmaxf(s[2], s[3]));
            mx = fmaxf(mx, __shfl_xor_sync(0xffffffffu, mx, 4));
            mx = fmaxf(mx, __shfl_xor_sync(0xffffffffu, mx, 2));
            mx = fmaxf(mx, __shfl_xor_sync(0xffffffffu, mx, 1));
            float mold = sm[q];
            float mnew = fmaxf(mold, mx);
            float p0 = __expf(s[0] - mnew);
            float p1 = __expf(s[1] - mnew);
            float p2 = __expf(s[2] - mnew);
            float p3 = __expf(s[3] - mnew);
            float ls = p0 + p1 + p2 + p3;
            ls += __shfl_xor_sync(0xffffffffu, ls, 4);
            ls += __shfl_xor_sync(0xffffffffu, ls, 2);
            ls += __shfl_xor_sync(0xffffffffu, ls, 1);
            float rsc = __expf(mold - mnew);
            if ((tid & 7) == 0) { sm[q] = mnew; sl[q] = sl[q]*rsc + ls; srs[q] = rsc; }
            Ps[(sk+0)*68 + q] = p0;
            Ps[(sk+1)*68 + q] = p1;
            Ps[(sk+2)*68 + q] = p2;
            Ps[(sk+3)*68 + q] = p3;
        }
        __syncthreads();

        // O = O*rescale + P V   (per-thread 4x4)
        float rsc[4] = {srs[py*4+0], srs[py*4+1], srs[py*4+2], srs[py*4+3]};
        #pragma unroll
        for (int i = 0; i < 4; i++)
            #pragma unroll
            for (int j = 0; j < 4; j++)
                acc[i][j] *= rsc[i];
        #pragma unroll
        for (int k = 0; k < 32; k++) {
            float4 pv = *(const float4*)(Ps + k*68 + py*4);
            float4 vv = *(const float4*)(Vs + k*64 + px*4);
            float pr[4] = {pv.x, pv.y, pv.z, pv.w};
            float vr[4] = {vv.x, vv.y, vv.z, vv.w};
            #pragma unroll
            for (int i = 0; i < 4; i++)
                #pragma unroll
                for (int j = 0; j < 4; j++)
                    acc[i][j] += pr[i]*vr[j];
        }
        __syncthreads();
    }

    // finalize: O /= l, write to (B, Sq, D)
    int b = bh >> 4, h = bh & 15;
    #pragma unroll
    for (int i = 0; i < 4; i++) {
        int q = py*4 + i;
        float inv = 1.f / sl[q];
        int qg = qt*64 + q;
        float4 o;
        o.x = acc[i][0]*inv; o.y = acc[i][1]*inv;
        o.z = acc[i][2]*inv; o.w = acc[i][3]*inv;
        *(float4*)(O + ((size_t)b*SQ + qg)*Dd + h*64 + px*4) = o;
    }
}

// ---------------- launch ----------------
extern "C" void kernel_launch(void* const* d_in, const int* in_sizes, int n_in,
                              void* d_out, int out_size)
{
    const float* x1   = (const float*)d_in[0];
    const float* x2   = (const float*)d_in[1];
    const float* x3   = (const float*)d_in[2];
    const float* xf1  = (const float*)d_in[3];
    const float* xf2  = (const float*)d_in[4];
    const float* xf3  = (const float*)d_in[5];
    const float* emb  = (const float*)d_in[6];
    const float* axw  = (const float*)d_in[7];
    const float* axb  = (const float*)d_in[8];
    const float* afw  = (const float*)d_in[9];
    const float* afb  = (const float*)d_in[10];
    const float* q_w  = (const float*)d_in[11];
    const float* q_b  = (const float*)d_in[12];
    const float* k_w  = (const float*)d_in[13];
    const float* k_b  = (const float*)d_in[14];
    const float* v_w  = (const float*)d_in[15];
    const float* v_b  = (const float*)d_in[16];
    const float* o_w  = (const float*)d_in[17];
    const float* o_b  = (const float*)d_in[18];
    float* out = (float*)d_out;

    float *mx, *mxf, *xn, *xfn, *Qp, *Kp, *Vp, *att;
    cudaGetSymbolAddress((void**)&mx,  g_mod_x);
    cudaGetSymbolAddress((void**)&mxf, g_mod_xf);
    cudaGetSymbolAddress((void**)&xn,  g_xn);
    cudaGetSymbolAddress((void**)&xfn, g_xfn);
    cudaGetSymbolAddress((void**)&Qp,  g_Qh);
    cudaGetSymbolAddress((void**)&Kp,  g_Kh);
    cudaGetSymbolAddress((void**)&Vp,  g_Vh);
    cudaGetSymbolAddress((void**)&att, g_att);

    // 1) adaLN modulation vectors
    adaln_mod_kernel<<<dim3(2*Dd/256,   Bc, NB), 256>>>(emb, axw, axb, mx,  2*Dd);
    adaln_mod_kernel<<<dim3(2*DXFc/256, Bc, NB), 256>>>(emb, afw, afb, mxf, 2*DXFc);

    // 2) LayerNorm + modulate
    ln_mod_kernel<<<NB*Bc*Tt, 256>>>(x1, x2, x3, mx,  xn,  Dd,   Bc*Tt, Tt);
    ln_mod_kernel<<<NB*Bc*Nf, 256>>>(xf1, xf2, xf3, mxf, xfn, DXFc, Bc*Nf, Nf);

    // 3) Q/K/V projections -> head layout
    gemm_kernel<0><<<dim3(Bc*Tt/128, Dd/128, NB), 256>>>(xn,  q_w, q_b, Qp, Bc*Tt, Dd, Dd,   Tt);
    gemm_kernel<0><<<dim3(Bc*Nf/128, Dd/128, NB), 256>>>(xfn, k_w, k_b, Kp, Bc*Nf, Dd, DXFc, Nf);
    gemm_kernel<0><<<dim3(Bc*Nf/128, Dd/128, NB), 256>>>(xfn, v_w, v_b, Vp, Bc*Nf, Dd, DXFc, Nf);

    // 4) attention
    attn_kernel<<<dim3(SQ/64, BHc), 256>>>(Qp, Kp, Vp, att);

    // 5) per-block output projection -> d_out (out0 | out1 | out2)
    gemm_kernel<1><<<dim3(Bc*Tt/128, Dd/128, NB), 256>>>(att, o_w, o_b, out, Bc*Tt, Dd, Dd, Tt);
}

// round 2
// speedup vs baseline: 1.3139x; 1.3139x over previous
#include <cuda_runtime.h>
#include <math.h>
#include <stdint.h>

// ---------------- problem constants ----------------
#define NB   3
#define Bc   4
#define Tt   512
#define Nf   256
#define Dd   1024
#define DXFc 512
#define Ee   1024
#define Hh   16
#define HDc  64
#define SQ   (NB*Tt)   // 1536
#define SKk  (NB*Nf)   // 768
#define BHc  (Bc*Hh)   // 64
#define EPSV 1e-6f

// ---------------- scratch ----------------
__device__ float g_mod_x [NB*Bc*2*Dd];
__device__ float g_mod_xf[NB*Bc*2*DXFc];
__device__ float g_xn [NB*Bc*Tt*Dd];
__device__ float g_xfn[NB*Bc*Nf*DXFc];
__device__ float g_Qh[(size_t)BHc*SQ*HDc];
__device__ float g_Kh[(size_t)BHc*SKk*HDc];
__device__ float g_Vh[(size_t)BHc*SKk*HDc];
__device__ float g_att[(size_t)Bc*SQ*Dd];

// ---------------- tf32 mma helpers ----------------
__device__ __forceinline__ uint32_t f2tf32(float f) {
    uint32_t u; asm("cvt.rna.tf32.f32 %0, %1;" : "=r"(u) : "f"(f)); return u;
}
__device__ __forceinline__ void mma_tf32(
    float& d0, float& d1, float& d2, float& d3,
    uint32_t a0, uint32_t a1, uint32_t a2, uint32_t a3,
    uint32_t b0, uint32_t b1)
{
    asm volatile(
        "mma.sync.aligned.m16n8k8.row.col.f32.tf32.tf32.f32 "
        "{%0,%1,%2,%3}, {%4,%5,%6,%7}, {%8,%9}, {%0,%1,%2,%3};"
        : "+f"(d0), "+f"(d1), "+f"(d2), "+f"(d3)
        : "r"(a0), "r"(a1), "r"(a2), "r"(a3), "r"(b0), "r"(b1));
}

// ---------------- kernel 1: adaLN modulation ----------------
__global__ __launch_bounds__(256) void adaln_mod_kernel(
    const float* __restrict__ emb, const float* __restrict__ w,
    const float* __restrict__ bvec, float* __restrict__ out, int twoD)
{
    __shared__ float se[Ee];
    int b = blockIdx.y, n = blockIdx.z;
    int tid = threadIdx.x;
    for (int i = tid*4; i < Ee; i += 256*4) {
        float4 v = *(const float4*)(emb + (size_t)b*Ee + i);
        se[i+0] = v.x / (1.f + __expf(-v.x));
        se[i+1] = v.y / (1.f + __expf(-v.y));
        se[i+2] = v.z / (1.f + __expf(-v.z));
        se[i+3] = v.w / (1.f + __expf(-v.w));
    }
    __syncthreads();
    int j = blockIdx.x*256 + tid;
    const float* wr = w + ((size_t)n*twoD + j)*Ee;
    float acc = 0.f;
    #pragma unroll 8
    for (int e = 0; e < Ee; e += 4) {
        float4 wv = *(const float4*)(wr + e);
        acc += se[e]*wv.x + se[e+1]*wv.y + se[e+2]*wv.z + se[e+3]*wv.w;
    }
    out[((size_t)n*Bc + b)*twoD + j] = acc + bvec[(size_t)n*twoD + j];
}

// ---------------- kernel 2: LayerNorm + modulate ----------------
__global__ __launch_bounds__(256) void ln_mod_kernel(
    const float* __restrict__ xa, const float* __restrict__ xb,
    const float* __restrict__ xc, const float* __restrict__ mod,
    float* __restrict__ xn, int dim, int rows_per_n, int rows_per_b)
{
    int r  = blockIdx.x;
    int n  = r / rows_per_n;
    int rr = r - n*rows_per_n;
    int b  = rr / rows_per_b;
    const float* xp = (n == 0 ? xa : (n == 1 ? xb : xc)) + (size_t)rr*dim;
    int tid = threadIdx.x;

    float s1 = 0.f, s2 = 0.f;
    for (int d = tid*4; d < dim; d += 1024) {
        float4 v = *(const float4*)(xp + d);
        s1 += v.x + v.y + v.z + v.w;
        s2 += v.x*v.x + v.y*v.y + v.z*v.z + v.w*v.w;
    }
    #pragma unroll
    for (int off = 16; off; off >>= 1) {
        s1 += __shfl_xor_sync(0xffffffffu, s1, off);
        s2 += __shfl_xor_sync(0xffffffffu, s2, off);
    }
    __shared__ float rs1[8], rs2[8];
    int wid = tid >> 5, lane = tid & 31;
    if (!lane) { rs1[wid] = s1; rs2[wid] = s2; }
    __syncthreads();
    s1 = rs1[0]+rs1[1]+rs1[2]+rs1[3]+rs1[4]+rs1[5]+rs1[6]+rs1[7];
    s2 = rs2[0]+rs2[1]+rs2[2]+rs2[3]+rs2[4]+rs2[5]+rs2[6]+rs2[7];

    float inv = 1.f / (float)dim;
    float mu  = s1 * inv;
    float var = s2 * inv - mu*mu;
    float rstd = rsqrtf(var + EPSV);

    const float* sc = mod + ((size_t)n*Bc + b)*2*dim;
    const float* sh = sc + dim;
    float* op = xn + (size_t)r*dim;
    for (int d = tid*4; d < dim; d += 1024) {
        float4 v = *(const float4*)(xp + d);
        float4 s = *(const float4*)(sc + d);
        float4 h = *(const float4*)(sh + d);
        float4 o;
        o.x = (v.x - mu)*rstd*(1.f + s.x) + h.x;
        o.y = (v.y - mu)*rstd*(1.f + s.y) + h.y;
        o.z = (v.z - mu)*rstd*(1.f + s.z) + h.z;
        o.w = (v.w - mu)*rstd*(1.f + s.w) + h.w;
        *(float4*)(op + d) = o;
    }
}

// ---------------- kernel 3: tf32 tensor-core GEMM  C = A * W^T + bias ----------------
// Block tile 128x128, k-slab 32, 8 warps each computing 64x32.
// MODE 0: activation per-n contiguous [n][M][K]; output scattered to head layout.
// MODE 1: A = g_att rows (b*NB+n)*L + t ; output [n][M][Nout].
template<int MODE>
__global__ __launch_bounds__(256) void gemm_tc_kernel(
    const float* __restrict__ A, const float* __restrict__ W,
    const float* __restrict__ bias, float* __restrict__ C,
    int M, int Nout, int K, int L)
{
    __shared__ uint32_t As[128][36];
    __shared__ uint32_t Bs[128][36];

    int n  = blockIdx.z;
    int mt = blockIdx.x, nt = blockIdx.y;
    int tid = threadIdx.x;
    int lrow = tid >> 1;
    int lk   = (tid & 1) * 16;
    int m0 = mt * 128;

    int mrow = m0 + lrow;
    const float* aptr;
    if (MODE == 0) {
        aptr = A + ((size_t)n*M + mrow)*K + lk;
    } else {
        int bq = mrow / L;
        int tq = mrow - bq*L;
        aptr = A + ((size_t)(bq*NB + n)*L + tq)*K + lk;
    }
    const float* wptr = W + ((size_t)n*Nout + nt*128 + lrow)*K + lk;

    int wid = tid >> 5, lane = tid & 31;
    int g = lane >> 2, t = lane & 3;
    int wm = wid >> 2, wn = wid & 3;        // 2 x 4 warp grid
    int warp_m = wm*64, warp_n = wn*32;

    float acc[4][4][4];
    #pragma unroll
    for (int mi = 0; mi < 4; mi++)
        #pragma unroll
        for (int ni = 0; ni < 4; ni++)
            #pragma unroll
            for (int r = 0; r < 4; r++) acc[mi][ni][r] = 0.f;

    float4 pa[4], pw[4];
    #pragma unroll
    for (int i = 0; i < 4; i++) {
        pa[i] = *(const float4*)(aptr + i*4);
        pw[i] = *(const float4*)(wptr + i*4);
    }

    int ntiles = K >> 5;
    for (int kt = 0; kt < ntiles; kt++) {
        #pragma unroll
        for (int i = 0; i < 4; i++) {
            As[lrow][lk+i*4+0] = f2tf32(pa[i].x);
            As[lrow][lk+i*4+1] = f2tf32(pa[i].y);
            As[lrow][lk+i*4+2] = f2tf32(pa[i].z);
            As[lrow][lk+i*4+3] = f2tf32(pa[i].w);
            Bs[lrow][lk+i*4+0] = f2tf32(pw[i].x);
            Bs[lrow][lk+i*4+1] = f2tf32(pw[i].y);
            Bs[lrow][lk+i*4+2] = f2tf32(pw[i].z);
            Bs[lrow][lk+i*4+3] = f2tf32(pw[i].w);
        }
        __syncthreads();

        if (kt + 1 < ntiles) {
            #pragma unroll
            for (int i = 0; i < 4; i++) {
                pa[i] = *(const float4*)(aptr + (kt+1)*32 + i*4);
                pw[i] = *(const float4*)(wptr + (kt+1)*32 + i*4);
            }
        }

        #pragma unroll
        for (int k0 = 0; k0 < 32; k0 += 8) {
            uint32_t af[4][4], bf[4][2];
            #pragma unroll
            for (int mi = 0; mi < 4; mi++) {
                int r0 = warp_m + mi*16 + g;
                af[mi][0] = As[r0  ][k0+t];
                af[mi][1] = As[r0+8][k0+t];
                af[mi][2] = As[r0  ][k0+t+4];
                af[mi][3] = As[r0+8][k0+t+4];
            }
            #pragma unroll
            for (int ni = 0; ni < 4; ni++) {
                int c = warp_n + ni*8 + g;
                bf[ni][0] = Bs[c][k0+t];
                bf[ni][1] = Bs[c][k0+t+4];
            }
            #pragma unroll
            for (int mi = 0; mi < 4; mi++)
                #pragma unroll
                for (int ni = 0; ni < 4; ni++)
                    mma_tf32(acc[mi][ni][0], acc[mi][ni][1],
                             acc[mi][ni][2], acc[mi][ni][3],
                             af[mi][0], af[mi][1], af[mi][2], af[mi][3],
                             bf[ni][0], bf[ni][1]);
        }
        __syncthreads();
    }

    // epilogue: C fragment (row g / g+8, cols t*2, t*2+1)
    #pragma unroll
    for (int mi = 0; mi < 4; mi++) {
        int rbase = m0 + warp_m + mi*16 + g;
        #pragma unroll
        for (int ni = 0; ni < 4; ni++) {
            int col = nt*128 + warp_n + ni*8 + t*2;
            float2 bv = *(const float2*)(bias + (size_t)n*Nout + col);
            #pragma unroll
            for (int h2 = 0; h2 < 2; h2++) {
                int row = rbase + h2*8;
                float2 o;
                o.x = acc[mi][ni][h2*2+0] + bv.x;
                o.y = acc[mi][ni][h2*2+1] + bv.y;
                if (MODE == 0) {
                    int bq = row / L; int l = row - bq*L;
                    int hh = col >> 6; int hd = col & 63;
                    size_t idx = (((size_t)(bq*Hh + hh))*((size_t)NB*L)
                                  + (size_t)n*L + l)*HDc + hd;
                    *(float2*)(C + idx) = o;
                } else {
                    *(float2*)(C + ((size_t)n*M + row)*Nout + col) = o;
                }
            }
        }
    }
}

// ---------------- kernel 4: flash attention (fp32) ----------------
__global__ __launch_bounds__(256) void attn_kernel(
    const float* __restrict__ Q, const float* __restrict__ K,
    const float* __restrict__ V, float* __restrict__ O)
{
    __shared__ __align__(16) float Qs[64*64];
    __shared__ __align__(16) float Kst[64*36];
    __shared__ __align__(16) float Ps[32*68];
    __shared__ __align__(16) float Vs[32*64];
    __shared__ float sm[64], sl[64], srs[64];

    int qt = blockIdx.x, bh = blockIdx.y;
    int tid = threadIdx.x;

    const float* Qb = Q + ((size_t)bh*SQ + qt*64)*HDc;
    for (int i = tid; i < 64*16; i += 256) {
        int r = i >> 4, c = (i & 15) * 4;
        float4 v = *(const float4*)(Qb + r*64 + c);
        v.x *= 0.125f; v.y *= 0.125f; v.z *= 0.125f; v.w *= 0.125f;
        *(float4*)(Qs + r*64 + c) = v;
    }
    if (tid < 64) { sm[tid] = -3.0e38f; sl[tid] = 0.f; }

    int sq = (tid >> 3) * 2;
    int sk = (tid & 7) * 4;
    int py = tid >> 4, px = tid & 15;

    float acc[4][4] = {};
    __syncthreads();

    for (int kt = 0; kt < SKk/32; kt++) {
        const float* Kb = K + ((size_t)bh*SKk + kt*32)*HDc;
        const float* Vb = V + ((size_t)bh*SKk + kt*32)*HDc;
        for (int i = tid; i < 32*16; i += 256) {
            int r = i >> 4, c = (i & 15) * 4;
            float4 kv = *(const float4*)(Kb + r*64 + c);
            Kst[(c+0)*36 + r] = kv.x;
            Kst[(c+1)*36 + r] = kv.y;
            Kst[(c+2)*36 + r] = kv.z;
            Kst[(c+3)*36 + r] = kv.w;
            *(float4*)(Vs + r*64 + c) = *(const float4*)(Vb + r*64 + c);
        }
        __syncthreads();

        float s0[4] = {}, s1[4] = {};
        #pragma unroll
        for (int d4 = 0; d4 < 16; d4++) {
            float4 qa = *(const float4*)(Qs + sq*64 + d4*4);
            float4 qb = *(const float4*)(Qs + (sq+1)*64 + d4*4);
            float qa_s[4] = {qa.x, qa.y, qa.z, qa.w};
            float qb_s[4] = {qb.x, qb.y, qb.z, qb.w};
            #pragma unroll
            for (int dd = 0; dd < 4; dd++) {
                float4 kv = *(const float4*)(Kst + (d4*4 + dd)*36 + sk);
                s0[0] += qa_s[dd]*kv.x; s0[1] += qa_s[dd]*kv.y;
                s0[2] += qa_s[dd]*kv.z; s0[3] += qa_s[dd]*kv.w;
                s1[0] += qb_s[dd]*kv.x; s1[1] += qb_s[dd]*kv.y;
                s1[2] += qb_s[dd]*kv.z; s1[3] += qb_s[dd]*kv.w;
            }
        }

        #pragma unroll
        for (int i = 0; i < 2; i++) {
            float* s = (i == 0) ? s0 : s1;
            int q = sq + i;
            float mx = fmaxf(fmaxf(s[0], s[1]), fmaxf(s[2], s[3]));
            mx = fmaxf(mx, __shfl_xor_sync(0xffffffffu, mx, 4));
            mx = fmaxf(mx, __shfl_xor_sync(0xffffffffu, mx, 2));
            mx = fmaxf(mx, __shfl_xor_sync(0xffffffffu, mx, 1));
            float mold = sm[q];
            float mnew = fmaxf(mold, mx);
            float p0 = __expf(s[0] - mnew);
            float p1 = __expf(s[1] - mnew);
            float p2 = __expf(s[2] - mnew);
            float p3 = __expf(s[3] - mnew);
            float ls = p0 + p1 + p2 + p3;
            ls += __shfl_xor_sync(0xffffffffu, ls, 4);
            ls += __shfl_xor_sync(0xffffffffu, ls, 2);
            ls += __shfl_xor_sync(0xffffffffu, ls, 1);
            float rsc = __expf(mold - mnew);
            if ((tid & 7) == 0) { sm[q] = mnew; sl[q] = sl[q]*rsc + ls; srs[q] = rsc; }
            Ps[(sk+0)*68 + q] = p0;
            Ps[(sk+1)*68 + q] = p1;
            Ps[(sk+2)*68 + q] = p2;
            Ps[(sk+3)*68 + q] = p3;
        }
        __syncthreads();

        float rsc[4] = {srs[py*4+0], srs[py*4+1], srs[py*4+2], srs[py*4+3]};
        #pragma unroll
        for (int i = 0; i < 4; i++)
            #pragma unroll
            for (int j = 0; j < 4; j++)
                acc[i][j] *= rsc[i];
        #pragma unroll
        for (int k = 0; k < 32; k++) {
            float4 pv = *(const float4*)(Ps + k*68 + py*4);
            float4 vv = *(const float4*)(Vs + k*64 + px*4);
            float pr[4] = {pv.x, pv.y, pv.z, pv.w};
            float vr[4] = {vv.x, vv.y, vv.z, vv.w};
            #pragma unroll
            for (int i = 0; i < 4; i++)
                #pragma unroll
                for (int j = 0; j < 4; j++)
                    acc[i][j] += pr[i]*vr[j];
        }
        __syncthreads();
    }

    int b = bh >> 4, h = bh & 15;
    #pragma unroll
    for (int i = 0; i < 4; i++) {
        int q = py*4 + i;
        float inv = 1.f / sl[q];
        int qg = qt*64 + q;
        float4 o;
        o.x = acc[i][0]*inv; o.y = acc[i][1]*inv;
        o.z = acc[i][2]*inv; o.w = acc[i][3]*inv;
        *(float4*)(O + ((size_t)b*SQ + qg)*Dd + h*64 + px*4) = o;
    }
}

// ---------------- launch ----------------
extern "C" void kernel_launch(void* const* d_in, const int* in_sizes, int n_in,
                              void* d_out, int out_size)
{
    const float* x1   = (const float*)d_in[0];
    const float* x2   = (const float*)d_in[1];
    const float* x3   = (const float*)d_in[2];
    const float* xf1  = (const float*)d_in[3];
    const float* xf2  = (const float*)d_in[4];
    const float* xf3  = (const float*)d_in[5];
    const float* emb  = (const float*)d_in[6];
    const float* axw  = (const float*)d_in[7];
    const float* axb  = (const float*)d_in[8];
    const float* afw  = (const float*)d_in[9];
    const float* afb  = (const float*)d_in[10];
    const float* q_w  = (const float*)d_in[11];
    const float* q_b  = (const float*)d_in[12];
    const float* k_w  = (const float*)d_in[13];
    const float* k_b  = (const float*)d_in[14];
    const float* v_w  = (const float*)d_in[15];
    const float* v_b  = (const float*)d_in[16];
    const float* o_w  = (const float*)d_in[17];
    const float* o_b  = (const float*)d_in[18];
    float* out = (float*)d_out;

    float *mx, *mxf, *xn, *xfn, *Qp, *Kp, *Vp, *att;
    cudaGetSymbolAddress((void**)&mx,  g_mod_x);
    cudaGetSymbolAddress((void**)&mxf, g_mod_xf);
    cudaGetSymbolAddress((void**)&xn,  g_xn);
    cudaGetSymbolAddress((void**)&xfn, g_xfn);
    cudaGetSymbolAddress((void**)&Qp,  g_Qh);
    cudaGetSymbolAddress((void**)&Kp,  g_Kh);
    cudaGetSymbolAddress((void**)&Vp,  g_Vh);
    cudaGetSymbolAddress((void**)&att, g_att);

    adaln_mod_kernel<<<dim3(2*Dd/256,   Bc, NB), 256>>>(emb, axw, axb, mx,  2*Dd);
    adaln_mod_kernel<<<dim3(2*DXFc/256, Bc, NB), 256>>>(emb, afw, afb, mxf, 2*DXFc);

    ln_mod_kernel<<<NB*Bc*Tt, 256>>>(x1, x2, x3, mx,  xn,  Dd,   Bc*Tt, Tt);
    ln_mod_kernel<<<NB*Bc*Nf, 256>>>(xf1, xf2, xf3, mxf, xfn, DXFc, Bc*Nf, Nf);

    gemm_tc_kernel<0><<<dim3(Bc*Tt/128, Dd/128, NB), 256>>>(xn,  q_w, q_b, Qp, Bc*Tt, Dd, Dd,   Tt);
    gemm_tc_kernel<0><<<dim3(Bc*Nf/128, Dd/128, NB), 256>>>(xfn, k_w, k_b, Kp, Bc*Nf, Dd, DXFc, Nf);
    gemm_tc_kernel<0><<<dim3(Bc*Nf/128, Dd/128, NB), 256>>>(xfn, v_w, v_b, Vp, Bc*Nf, Dd, DXFc, Nf);

    attn_kernel<<<dim3(SQ/64, BHc), 256>>>(Qp, Kp, Vp, att);

    gemm_tc_kernel<1><<<dim3(Bc*Tt/128, Dd/128, NB), 256>>>(att, o_w, o_b, out, Bc*Tt, Dd, Dd, Tt);
}

// round 3
// speedup vs baseline: 2.2705x; 1.7280x over previous
#include <cuda_runtime.h>
#include <math.h>
#include <stdint.h>

// ---------------- problem constants ----------------
#define NB   3
#define Bc   4
#define Tt   512
#define Nf   256
#define Dd   1024
#define DXFc 512
#define Ee   1024
#define Hh   16
#define HDc  64
#define SQ   (NB*Tt)   // 1536
#define SKk  (NB*Nf)   // 768
#define BHc  (Bc*Hh)   // 64
#define EPSV 1e-6f

// k-interleave: within each 8-group, col t -> 2t, col t+4 -> 2t+1
#define KMAP(k) (((k) & ~7) | (((k) & 3) << 1) | (((k) >> 2) & 1))

// ---------------- scratch ----------------
__device__ float g_mod_x [NB*Bc*2*Dd];
__device__ float g_mod_xf[NB*Bc*2*DXFc];
__device__ float g_xn [NB*Bc*Tt*Dd];
__device__ float g_xfn[NB*Bc*Nf*DXFc];
__device__ float g_Qh[(size_t)BHc*SQ*HDc];
__device__ float g_Kh[(size_t)BHc*SKk*HDc];
__device__ float g_Vh[(size_t)BHc*SKk*HDc];
__device__ float g_att[(size_t)Bc*SQ*Dd];

// ---------------- tf32 mma helpers ----------------
__device__ __forceinline__ uint32_t f2tf32(float f) {
    uint32_t u; asm("cvt.rna.tf32.f32 %0, %1;" : "=r"(u) : "f"(f)); return u;
}
__device__ __forceinline__ void mma_tf32(
    float& d0, float& d1, float& d2, float& d3,
    uint32_t a0, uint32_t a1, uint32_t a2, uint32_t a3,
    uint32_t b0, uint32_t b1)
{
    asm volatile(
        "mma.sync.aligned.m16n8k8.row.col.f32.tf32.tf32.f32 "
        "{%0,%1,%2,%3}, {%4,%5,%6,%7}, {%8,%9}, {%0,%1,%2,%3};"
        : "+f"(d0), "+f"(d1), "+f"(d2), "+f"(d3)
        : "r"(a0), "r"(a1), "r"(a2), "r"(a3), "r"(b0), "r"(b1));
}

// ---------------- kernel 1: adaLN modulation ----------------
__global__ __launch_bounds__(256) void adaln_mod_kernel(
    const float* __restrict__ emb, const float* __restrict__ w,
    const float* __restrict__ bvec, float* __restrict__ out, int twoD)
{
    __shared__ float se[Ee];
    int b = blockIdx.y, n = blockIdx.z;
    int tid = threadIdx.x;
    for (int i = tid*4; i < Ee; i += 256*4) {
        float4 v = *(const float4*)(emb + (size_t)b*Ee + i);
        se[i+0] = v.x / (1.f + __expf(-v.x));
        se[i+1] = v.y / (1.f + __expf(-v.y));
        se[i+2] = v.z / (1.f + __expf(-v.z));
        se[i+3] = v.w / (1.f + __expf(-v.w));
    }
    __syncthreads();
    int j = blockIdx.x*256 + tid;
    const float* wr = w + ((size_t)n*twoD + j)*Ee;
    float acc = 0.f;
    #pragma unroll 8
    for (int e = 0; e < Ee; e += 4) {
        float4 wv = *(const float4*)(wr + e);
        acc += se[e]*wv.x + se[e+1]*wv.y + se[e+2]*wv.z + se[e+3]*wv.w;
    }
    out[((size_t)n*Bc + b)*twoD + j] = acc + bvec[(size_t)n*twoD + j];
}

// ---------------- kernel 2: LayerNorm + modulate ----------------
__global__ __launch_bounds__(256) void ln_mod_kernel(
    const float* __restrict__ xa, const float* __restrict__ xb,
    const float* __restrict__ xc, const float* __restrict__ mod,
    float* __restrict__ xn, int dim, int rows_per_n, int rows_per_b)
{
    int r  = blockIdx.x;
    int n  = r / rows_per_n;
    int rr = r - n*rows_per_n;
    int b  = rr / rows_per_b;
    const float* xp = (n == 0 ? xa : (n == 1 ? xb : xc)) + (size_t)rr*dim;
    int tid = threadIdx.x;

    float s1 = 0.f, s2 = 0.f;
    for (int d = tid*4; d < dim; d += 1024) {
        float4 v = *(const float4*)(xp + d);
        s1 += v.x + v.y + v.z + v.w;
        s2 += v.x*v.x + v.y*v.y + v.z*v.z + v.w*v.w;
    }
    #pragma unroll
    for (int off = 16; off; off >>= 1) {
        s1 += __shfl_xor_sync(0xffffffffu, s1, off);
        s2 += __shfl_xor_sync(0xffffffffu, s2, off);
    }
    __shared__ float rs1[8], rs2[8];
    int wid = tid >> 5, lane = tid & 31;
    if (!lane) { rs1[wid] = s1; rs2[wid] = s2; }
    __syncthreads();
    s1 = rs1[0]+rs1[1]+rs1[2]+rs1[3]+rs1[4]+rs1[5]+rs1[6]+rs1[7];
    s2 = rs2[0]+rs2[1]+rs2[2]+rs2[3]+rs2[4]+rs2[5]+rs2[6]+rs2[7];

    float inv = 1.f / (float)dim;
    float mu  = s1 * inv;
    float var = s2 * inv - mu*mu;
    float rstd = rsqrtf(var + EPSV);

    const float* sc = mod + ((size_t)n*Bc + b)*2*dim;
    const float* sh = sc + dim;
    float* op = xn + (size_t)r*dim;
    for (int d = tid*4; d < dim; d += 1024) {
        float4 v = *(const float4*)(xp + d);
        float4 s = *(const float4*)(sc + d);
        float4 h = *(const float4*)(sh + d);
        float4 o;
        o.x = (v.x - mu)*rstd*(1.f + s.x) + h.x;
        o.y = (v.y - mu)*rstd*(1.f + s.y) + h.y;
        o.z = (v.z - mu)*rstd*(1.f + s.z) + h.z;
        o.w = (v.w - mu)*rstd*(1.f + s.w) + h.w;
        *(float4*)(op + d) = o;
    }
}

// ---------------- kernel 3: tf32 tensor-core GEMM ----------------
template<int MODE>
__global__ __launch_bounds__(256, 2) void gemm_tc_kernel(
    const float* __restrict__ A, const float* __restrict__ W,
    const float* __restrict__ bias, float* __restrict__ C,
    int M, int Nout, int K, int L)
{
    __shared__ uint32_t As[128][36];
    __shared__ uint32_t Bs[128][36];

    int n  = blockIdx.z;
    int mt = blockIdx.x, nt = blockIdx.y;
    int tid = threadIdx.x;
    int lrow = tid >> 1;
    int lk   = (tid & 1) * 16;
    int m0 = mt * 128;

    int mrow = m0 + lrow;
    const float* aptr;
    if (MODE == 0) {
        aptr = A + ((size_t)n*M + mrow)*K + lk;
    } else {
        int bq = mrow / L;
        int tq = mrow - bq*L;
        aptr = A + ((size_t)(bq*NB + n)*L + tq)*K + lk;
    }
    const float* wptr = W + ((size_t)n*Nout + nt*128 + lrow)*K + lk;

    int wid = tid >> 5, lane = tid & 31;
    int g = lane >> 2, t = lane & 3;
    int wm = wid >> 2, wn = wid & 3;
    int warp_m = wm*64, warp_n = wn*32;

    float acc[4][4][4];
    #pragma unroll
    for (int mi = 0; mi < 4; mi++)
        #pragma unroll
        for (int ni = 0; ni < 4; ni++)
            #pragma unroll
            for (int r = 0; r < 4; r++) acc[mi][ni][r] = 0.f;

    float4 pa[4], pw[4];
    #pragma unroll
    for (int i = 0; i < 4; i++) {
        pa[i] = *(const float4*)(aptr + i*4);
        pw[i] = *(const float4*)(wptr + i*4);
    }

    int ntiles = K >> 5;
    for (int kt = 0; kt < ntiles; kt++) {
        #pragma unroll
        for (int i = 0; i < 4; i++) {
            As[lrow][lk+i*4+0] = f2tf32(pa[i].x);
            As[lrow][lk+i*4+1] = f2tf32(pa[i].y);
            As[lrow][lk+i*4+2] = f2tf32(pa[i].z);
            As[lrow][lk+i*4+3] = f2tf32(pa[i].w);
            Bs[lrow][lk+i*4+0] = f2tf32(pw[i].x);
            Bs[lrow][lk+i*4+1] = f2tf32(pw[i].y);
            Bs[lrow][lk+i*4+2] = f2tf32(pw[i].z);
            Bs[lrow][lk+i*4+3] = f2tf32(pw[i].w);
        }
        __syncthreads();

        if (kt + 1 < ntiles) {
            #pragma unroll
            for (int i = 0; i < 4; i++) {
                pa[i] = *(const float4*)(aptr + (kt+1)*32 + i*4);
                pw[i] = *(const float4*)(wptr + (kt+1)*32 + i*4);
            }
        }

        #pragma unroll
        for (int k0 = 0; k0 < 32; k0 += 8) {
            uint32_t af[4][4], bf[4][2];
            #pragma unroll
            for (int mi = 0; mi < 4; mi++) {
                int r0 = warp_m + mi*16 + g;
                af[mi][0] = As[r0  ][k0+t];
                af[mi][1] = As[r0+8][k0+t];
                af[mi][2] = As[r0  ][k0+t+4];
                af[mi][3] = As[r0+8][k0+t+4];
            }
            #pragma unroll
            for (int ni = 0; ni < 4; ni++) {
                int c = warp_n + ni*8 + g;
                bf[ni][0] = Bs[c][k0+t];
                bf[ni][1] = Bs[c][k0+t+4];
            }
            #pragma unroll
            for (int mi = 0; mi < 4; mi++)
                #pragma unroll
                for (int ni = 0; ni < 4; ni++)
                    mma_tf32(acc[mi][ni][0], acc[mi][ni][1],
                             acc[mi][ni][2], acc[mi][ni][3],
                             af[mi][0], af[mi][1], af[mi][2], af[mi][3],
                             bf[ni][0], bf[ni][1]);
        }
        __syncthreads();
    }

    #pragma unroll
    for (int mi = 0; mi < 4; mi++) {
        int rbase = m0 + warp_m + mi*16 + g;
        #pragma unroll
        for (int ni = 0; ni < 4; ni++) {
            int col = nt*128 + warp_n + ni*8 + t*2;
            float2 bv = *(const float2*)(bias + (size_t)n*Nout + col);
            #pragma unroll
            for (int h2 = 0; h2 < 2; h2++) {
                int row = rbase + h2*8;
                float2 o;
                o.x = acc[mi][ni][h2*2+0] + bv.x;
                o.y = acc[mi][ni][h2*2+1] + bv.y;
                if (MODE == 0) {
                    int bq = row / L; int l = row - bq*L;
                    int hh = col >> 6; int hd = col & 63;
                    size_t idx = (((size_t)(bq*Hh + hh))*((size_t)NB*L)
                                  + (size_t)n*L + l)*HDc + hd;
                    *(float2*)(C + idx) = o;
                } else {
                    *(float2*)(C + ((size_t)n*M + row)*Nout + col) = o;
                }
            }
        }
    }
}

// ---------------- kernel 4: tf32 tensor-core flash attention ----------------
// BLK_Q=128, BLK_K=64. 8 warps, warp w owns q-rows [w*16, w*16+16) x all 64 k.
// smem words: Qs[128][72] kmap'd | Ks[64][72] kmap'd | Vs[64][72] natural | Ps[128][72] kmap'd
#define ATTN_SMEM_BYTES (27648*4)
__global__ __launch_bounds__(256, 2) void attn_tc_kernel(
    const float* __restrict__ Q, const float* __restrict__ K,
    const float* __restrict__ V, float* __restrict__ O)
{
    extern __shared__ uint32_t sh[];
    uint32_t* Qs = sh;            // [128][72]
    uint32_t* Ks = sh + 9216;     // [64][72]
    uint32_t* Vs = sh + 13824;    // [64][72]
    uint32_t* Ps = sh + 18432;    // [128][72]

    int qt = blockIdx.x, bh = blockIdx.y;
    int tid = threadIdx.x;
    int wid = tid >> 5, lane = tid & 31;
    int g = lane >> 2, t = lane & 3;
    int r0 = wid*16 + g, r1 = r0 + 8;

    // load Q tile (scaled by 1/8), kmap layout
    {
        int lrow = tid >> 1, lk = (tid & 1) * 32;
        const float* src = Q + ((size_t)bh*SQ + qt*128 + lrow)*HDc + lk;
        uint32_t* dst = Qs + lrow*72;
        #pragma unroll
        for (int j = 0; j < 8; j++) {
            float4 v = *(const float4*)(src + j*4);
            int d0 = lk + j*4;
            dst[KMAP(d0+0)] = f2tf32(v.x*0.125f);
            dst[KMAP(d0+1)] = f2tf32(v.y*0.125f);
            dst[KMAP(d0+2)] = f2tf32(v.z*0.125f);
            dst[KMAP(d0+3)] = f2tf32(v.w*0.125f);
        }
    }

    float m0 = -3.0e38f, m1 = -3.0e38f, l0 = 0.f, l1 = 0.f;
    float acc[8][4];
    #pragma unroll
    for (int ni = 0; ni < 8; ni++)
        #pragma unroll
        for (int r = 0; r < 4; r++) acc[ni][r] = 0.f;

    for (int kt = 0; kt < SKk/64; kt++) {
        // load K (kmap) + V (natural) tiles
        {
            int lrow = tid >> 2, lk = (tid & 3) * 16;
            const float* kp = K + ((size_t)bh*SKk + kt*64 + lrow)*HDc + lk;
            const float* vp = V + ((size_t)bh*SKk + kt*64 + lrow)*HDc + lk;
            uint32_t* kd = Ks + lrow*72;
            uint32_t* vd = Vs + lrow*72 + lk;
            #pragma unroll
            for (int j = 0; j < 4; j++) {
                float4 kv = *(const float4*)(kp + j*4);
                int d0 = lk + j*4;
                kd[KMAP(d0+0)] = f2tf32(kv.x);
                kd[KMAP(d0+1)] = f2tf32(kv.y);
                kd[KMAP(d0+2)] = f2tf32(kv.z);
                kd[KMAP(d0+3)] = f2tf32(kv.w);
                float4 vv = *(const float4*)(vp + j*4);
                uint4 pk;
                pk.x = f2tf32(vv.x); pk.y = f2tf32(vv.y);
                pk.z = f2tf32(vv.z); pk.w = f2tf32(vv.w);
                *(uint4*)(vd + j*4) = pk;
            }
        }
        __syncthreads();

        // S = Q K^T   (warp: 16 rows x 64 cols)
        float sf[8][4];
        #pragma unroll
        for (int ni = 0; ni < 8; ni++)
            #pragma unroll
            for (int r = 0; r < 4; r++) sf[ni][r] = 0.f;

        #pragma unroll
        for (int k0 = 0; k0 < 8; k0++) {
            uint2 aA = *(const uint2*)&Qs[r0*72 + k0*8 + 2*t];
            uint2 aB = *(const uint2*)&Qs[r1*72 + k0*8 + 2*t];
            #pragma unroll
            for (int ni = 0; ni < 8; ni++) {
                uint2 b = *(const uint2*)&Ks[(ni*8+g)*72 + k0*8 + 2*t];
                mma_tf32(sf[ni][0], sf[ni][1], sf[ni][2], sf[ni][3],
                         aA.x, aB.x, aA.y, aB.y, b.x, b.y);
            }
        }

        // online softmax (rows r0: sf[.][0..1], r1: sf[.][2..3])
        float mx0 = -3.0e38f, mx1 = -3.0e38f;
        #pragma unroll
        for (int ni = 0; ni < 8; ni++) {
            mx0 = fmaxf(mx0, fmaxf(sf[ni][0], sf[ni][1]));
            mx1 = fmaxf(mx1, fmaxf(sf[ni][2], sf[ni][3]));
        }
        mx0 = fmaxf(mx0, __shfl_xor_sync(0xffffffffu, mx0, 1));
        mx0 = fmaxf(mx0, __shfl_xor_sync(0xffffffffu, mx0, 2));
        mx1 = fmaxf(mx1, __shfl_xor_sync(0xffffffffu, mx1, 1));
        mx1 = fmaxf(mx1, __shfl_xor_sync(0xffffffffu, mx1, 2));
        float mn0 = fmaxf(m0, mx0), mn1 = fmaxf(m1, mx1);
        float rs0 = __expf(m0 - mn0), rs1 = __expf(m1 - mn1);
        float ls0 = 0.f, ls1 = 0.f;
        #pragma unroll
        for (int ni = 0; ni < 8; ni++) {
            sf[ni][0] = __expf(sf[ni][0] - mn0);
            sf[ni][1] = __expf(sf[ni][1] - mn0);
            sf[ni][2] = __expf(sf[ni][2] - mn1);
            sf[ni][3] = __expf(sf[ni][3] - mn1);
            ls0 += sf[ni][0] + sf[ni][1];
            ls1 += sf[ni][2] + sf[ni][3];
        }
        ls0 += __shfl_xor_sync(0xffffffffu, ls0, 1);
        ls0 += __shfl_xor_sync(0xffffffffu, ls0, 2);
        ls1 += __shfl_xor_sync(0xffffffffu, ls1, 1);
        ls1 += __shfl_xor_sync(0xffffffffu, ls1, 2);
        l0 = l0*rs0 + ls0;  m0 = mn0;
        l1 = l1*rs1 + ls1;  m1 = mn1;
        #pragma unroll
        for (int ni = 0; ni < 8; ni++) {
            acc[ni][0] *= rs0; acc[ni][1] *= rs0;
            acc[ni][2] *= rs1; acc[ni][3] *= rs1;
        }

        // store P (kmap layout over key dim), warp-local
        #pragma unroll
        for (int ni = 0; ni < 8; ni++) {
            Ps[r0*72 + ni*8 + KMAP(2*t)  ] = f2tf32(sf[ni][0]);
            Ps[r0*72 + ni*8 + KMAP(2*t+1)] = f2tf32(sf[ni][1]);
            Ps[r1*72 + ni*8 + KMAP(2*t)  ] = f2tf32(sf[ni][2]);
            Ps[r1*72 + ni*8 + KMAP(2*t+1)] = f2tf32(sf[ni][3]);
        }
        __syncwarp();

        // O += P V   (A = P[16 x 64keys], B = V[d][key] read from natural Vs)
        #pragma unroll
        for (int k0 = 0; k0 < 8; k0++) {
            uint2 aA = *(const uint2*)&Ps[r0*72 + k0*8 + 2*t];
            uint2 aB = *(const uint2*)&Ps[r1*72 + k0*8 + 2*t];
            #pragma unroll
            for (int ni = 0; ni < 8; ni++) {
                uint32_t b0 = Vs[(k0*8 + t    )*72 + ni*8 + g];
                uint32_t b1 = Vs[(k0*8 + t + 4)*72 + ni*8 + g];
                mma_tf32(acc[ni][0], acc[ni][1], acc[ni][2], acc[ni][3],
                         aA.x, aB.x, aA.y, aB.y, b0, b1);
            }
        }
        __syncthreads();
    }

    // finalize
    float inv0 = 1.f / l0, inv1 = 1.f / l1;
    int b = bh >> 4, h = bh & 15;
    int q0 = qt*128 + r0, q1 = q0 + 8;
    float* O0 = O + ((size_t)b*SQ + q0)*Dd + h*64;
    float* O1 = O + ((size_t)b*SQ + q1)*Dd + h*64;
    #pragma unroll
    for (int ni = 0; ni < 8; ni++) {
        int col = ni*8 + 2*t;
        float2 o0, o1;
        o0.x = acc[ni][0]*inv0; o0.y = acc[ni][1]*inv0;
        o1.x = acc[ni][2]*inv1; o1.y = acc[ni][3]*inv1;
        *(float2*)(O0 + col) = o0;
        *(float2*)(O1 + col) = o1;
    }
}

// ---------------- launch ----------------
extern "C" void kernel_launch(void* const* d_in, const int* in_sizes, int n_in,
                              void* d_out, int out_size)
{
    const float* x1   = (const float*)d_in[0];
    const float* x2   = (const float*)d_in[1];
    const float* x3   = (const float*)d_in[2];
    const float* xf1  = (const float*)d_in[3];
    const float* xf2  = (const float*)d_in[4];
    const float* xf3  = (const float*)d_in[5];
    const float* emb  = (const float*)d_in[6];
    const float* axw  = (const float*)d_in[7];
    const float* axb  = (const float*)d_in[8];
    const float* afw  = (const float*)d_in[9];
    const float* afb  = (const float*)d_in[10];
    const float* q_w  = (const float*)d_in[11];
    const float* q_b  = (const float*)d_in[12];
    const float* k_w  = (const float*)d_in[13];
    const float* k_b  = (const float*)d_in[14];
    const float* v_w  = (const float*)d_in[15];
    const float* v_b  = (const float*)d_in[16];
    const float* o_w  = (const float*)d_in[17];
    const float* o_b  = (const float*)d_in[18];
    float* out = (float*)d_out;

    float *mx, *mxf, *xn, *xfn, *Qp, *Kp, *Vp, *att;
    cudaGetSymbolAddress((void**)&mx,  g_mod_x);
    cudaGetSymbolAddress((void**)&mxf, g_mod_xf);
    cudaGetSymbolAddress((void**)&xn,  g_xn);
    cudaGetSymbolAddress((void**)&xfn, g_xfn);
    cudaGetSymbolAddress((void**)&Qp,  g_Qh);
    cudaGetSymbolAddress((void**)&Kp,  g_Kh);
    cudaGetSymbolAddress((void**)&Vp,  g_Vh);
    cudaGetSymbolAddress((void**)&att, g_att);

    cudaFuncSetAttribute(attn_tc_kernel,
        cudaFuncAttributeMaxDynamicSharedMemorySize, ATTN_SMEM_BYTES);

    adaln_mod_kernel<<<dim3(2*Dd/256,   Bc, NB), 256>>>(emb, axw, axb, mx,  2*Dd);
    adaln_mod_kernel<<<dim3(2*DXFc/256, Bc, NB), 256>>>(emb, afw, afb, mxf, 2*DXFc);

    ln_mod_kernel<<<NB*Bc*Tt, 256>>>(x1, x2, x3, mx,  xn,  Dd,   Bc*Tt, Tt);
    ln_mod_kernel<<<NB*Bc*Nf, 256>>>(xf1, xf2, xf3, mxf, xfn, DXFc, Bc*Nf, Nf);

    gemm_tc_kernel<0><<<dim3(Bc*Tt/128, Dd/128, NB), 256>>>(xn,  q_w, q_b, Qp, Bc*Tt, Dd, Dd,   Tt);
    gemm_tc_kernel<0><<<dim3(Bc*Nf/128, Dd/128, NB), 256>>>(xfn, k_w, k_b, Kp, Bc*Nf, Dd, DXFc, Nf);
    gemm_tc_kernel<0><<<dim3(Bc*Nf/128, Dd/128, NB), 256>>>(xfn, v_w, v_b, Vp, Bc*Nf, Dd, DXFc, Nf);

    attn_tc_kernel<<<dim3(SQ/128, BHc), 256, ATTN_SMEM_BYTES>>>(Qp, Kp, Vp, att);

    gemm_tc_kernel<1><<<dim3(Bc*Tt/128, Dd/128, NB), 256>>>(att, o_w, o_b, out, Bc*Tt, Dd, Dd, Tt);
}